// round 9
// baseline (speedup 1.0000x reference)
#include <cuda_runtime.h>
#include <cstdint>

#define B_    8
#define N_    2048
#define D_    1024
#define E_    64
#define CAP_  80
#define TOK_  (B_ * N_)                 // 16384
#define TPB_  256                       // threads per block (4 compute + 4 fill warps)
#define NCHUNK_ 128                     // gate chunks (128 tokens each)
#define OUTSZ_ 83886080ULL              // B*N*E*CAP
#define S_AS  65                        // As row stride (odd -> conflict-free columns)

#define GRID_TOTAL 148
#define FILL4_     41943040L            // (2*OUTSZ_)/4  total float4 to zero
#define NWARPS_    (GRID_TOTAL * 8)     // 1184
#define PERWARP_   35425L               // ceil(FILL4_/1184)

// ---------------- scratch (device globals) ----------------
__device__ int   g_hist1[NCHUNK_ * E_];
__device__ int   g_hist2[NCHUNK_ * E_];
__device__ float g_proxyp[NCHUNK_ * E_];
__device__ unsigned int g_bar;          // monotonic ticket barrier (replay-safe)

extern __shared__ float dynsh[];

__device__ __forceinline__ void bar128() {
    asm volatile("bar.sync 1, 128;" ::: "memory");
}

__device__ __forceinline__ void stg_cs_zero(float4* p) {
    asm volatile("st.global.cs.v4.f32 [%0], {%1, %1, %1, %1};"
                 :: "l"(p), "f"(0.0f) : "memory");
}

// one warp fills its static slice
__device__ __forceinline__ void fill_warp(float4* __restrict__ o4, int gwid, int lane) {
    long lo = (long)gwid * PERWARP_;
    long hi = lo + PERWARP_;
    if (hi > FILL4_) hi = FILL4_;
    long i = lo + lane;
    // unrolled-by-4 main loop for MLP
    for (; i + 96 < hi; i += 128) {
        stg_cs_zero(o4 + i);
        stg_cs_zero(o4 + i + 32);
        stg_cs_zero(o4 + i + 64);
        stg_cs_zero(o4 + i + 96);
    }
    for (; i < hi; i += 32) stg_cs_zero(o4 + i);
}

__device__ __forceinline__ void grid_barrier(int tid) {
    __syncthreads();
    if (tid == 0) {
        __threadfence();                                  // fills + hists visible
        unsigned int old = atomicAdd(&g_bar, 1u);
        unsigned int target = old - (old % GRID_TOTAL) + GRID_TOTAL;
        unsigned int v;
        do {
            asm volatile("ld.acquire.gpu.u32 %0, [%1];" : "=r"(v) : "l"(&g_bar));
        } while (v < target);
    }
    __syncthreads();
}

__global__ __launch_bounds__(TPB_) void k_fused(
    const float* __restrict__ x,
    const float* __restrict__ w,
    const float* __restrict__ noise,
    float* __restrict__ out)
{
    const int tid  = threadIdx.x;
    const int wid  = tid >> 5;
    const int lane = tid & 31;
    const int gwid = blockIdx.x * 8 + wid;
    float4* __restrict__ o4 = (float4*)out;

    __shared__ int   s_meta[128];        // idx1 | idx2<<6 | keep<<12
    __shared__ float s_g1[128];
    __shared__ float s_g2[128];
    __shared__ float s_inv[128];
    __shared__ int   s_i1[128];
    __shared__ int   s_i2[128];
    __shared__ int   sp1[128];
    __shared__ int   sp2[128];

    // ================= Phase A =================
    if (blockIdx.x < NCHUNK_ && wid < 4) {
        // ---- compute half: GEMM + softmax + top2 (tid in 0..127) ----
        float* As = dynsh;                       // [128][S_AS]
        float* Ws = dynsh + 128 * S_AS;          // [64][64]

        const int ty  = tid >> 3;
        const int tx  = tid & 7;
        const int t0  = ty * 8;
        const int gt0 = blockIdx.x * 128;
        const float* xblk = x + (size_t)gt0 * D_;

        unsigned long long acc[8][4];
        #pragma unroll
        for (int i = 0; i < 8; ++i)
            #pragma unroll
            for (int j = 0; j < 4; ++j) acc[i][j] = 0ULL;

        for (int kc = 0; kc < 16; ++kc) {
            #pragma unroll
            for (int i = 0; i < 16; ++i) {
                int idx = tid + i * 128;
                int r = idx >> 4, c4 = idx & 15;
                float4 v = *(const float4*)(xblk + (size_t)r * D_ + kc * 64 + c4 * 4);
                float* p = &As[r * S_AS + c4 * 4];
                p[0] = v.x; p[1] = v.y; p[2] = v.z; p[3] = v.w;
            }
            #pragma unroll
            for (int i = 0; i < 8; ++i) {
                int idx = tid + i * 128;
                int kr = idx >> 4, c4 = idx & 15;
                float4 v = *(const float4*)(w + (size_t)(kc * 64 + kr) * E_ + c4 * 4);
                *(float4*)&Ws[kr * 64 + c4 * 4] = v;
            }
            bar128();

            #pragma unroll 8
            for (int k = 0; k < 64; ++k) {
                unsigned long long a2[8], w2[4];
                #pragma unroll
                for (int i = 0; i < 8; ++i) {
                    float a = As[(t0 + i) * S_AS + k];
                    asm("mov.b64 %0, {%1, %1};" : "=l"(a2[i]) : "f"(a));
                }
                #pragma unroll
                for (int j = 0; j < 4; ++j)
                    w2[j] = *(const unsigned long long*)&Ws[k * 64 + 2 * tx + 16 * j];
                #pragma unroll
                for (int i = 0; i < 8; ++i)
                    #pragma unroll
                    for (int j = 0; j < 4; ++j)
                        asm("fma.rn.f32x2 %0, %1, %2, %0;" : "+l"(acc[i][j]) : "l"(a2[i]), "l"(w2[j]));
            }
            bar128();
        }

        // logits -> As[t][e]
        #pragma unroll
        for (int i = 0; i < 8; ++i)
            #pragma unroll
            for (int j = 0; j < 4; ++j) {
                float lo, hi;
                asm("mov.b64 {%0, %1}, %2;" : "=f"(lo), "=f"(hi) : "l"(acc[i][j]));
                As[(t0 + i) * S_AS + 2 * tx + 16 * j]     = lo;
                As[(t0 + i) * S_AS + 2 * tx + 16 * j + 1] = hi;
            }
        bar128();

        // per-token: softmax + top2 + gates
        {
            const int t = tid;
            float m1 = -1e30f, m2 = -1e30f;
            int i1 = 0, i2 = 0;
            #pragma unroll 8
            for (int e = 0; e < E_; ++e) {
                float l = As[t * S_AS + e];
                if (l > m1) { m2 = m1; i2 = i1; m1 = l; i1 = e; }
                else if (l > m2) { m2 = l; i2 = e; }
            }
            float s = 0.0f;
            #pragma unroll 8
            for (int e = 0; e < E_; ++e) {
                float p = expf(As[t * S_AS + e] - m1);
                As[t * S_AS + e] = p;
                s += p;
            }
            float inv = 1.0f / s;
            float g1 = inv;
            float g2 = expf(m2 - m1) * inv;
            float den = g1 + g2 + 1e-9f;
            g1 /= den; g2 /= den;

            int keep = (noise[gt0 + t] < (g2 / 0.2f)) ? 1 : 0;
            s_meta[t] = i1 | (i2 << 6) | (keep << 12);
            s_g1[t] = g1; s_g2[t] = g2;
            s_i1[t] = i1;
            s_i2[t] = keep ? i2 : -1;
            s_inv[t] = inv;
        }
        bar128();

        // per-expert partials -> global
        if (tid < E_) {
            const int e = tid;
            float ps = 0.0f; int c1 = 0, c2 = 0;
            #pragma unroll 4
            for (int t = 0; t < 128; ++t) {
                ps += As[t * S_AS + e] * s_inv[t];
                c1 += (s_i1[t] == e);
                c2 += (s_i2[t] == e);
            }
            int o = blockIdx.x * E_ + e;
            g_proxyp[o] = ps;
            g_hist1[o] = c1;
            g_hist2[o] = c2;
        }

        // compute warps contribute their fill share after the math
        fill_warp(o4, gwid, lane);
    } else {
        // fill warps (upper half of gate blocks, all warps of extra blocks)
        fill_warp(o4, gwid, lane);
    }

    // ================= barrier =================
    grid_barrier(tid);

    // ================= Phase B =================
    if (blockIdx.x < NCHUNK_) {
        const int chunk = blockIdx.x;
        const int b = chunk >> 4;
        const int myc = chunk & 15;
        const int cg0 = b * 16;

        if (tid < E_) {
            const int e = tid;
            int off1 = 0, tot1 = 0, off2p = 0;
            #pragma unroll
            for (int c = 0; c < 16; ++c) {
                int h1 = g_hist1[(cg0 + c) * E_ + e];
                int h2 = g_hist2[(cg0 + c) * E_ + e];
                if (c < myc) { off1 += h1; off2p += h2; }
                tot1 += h1;
            }
            int c1t = tot1 < CAP_ ? tot1 : CAP_;
            int c1 = off1;
            int c2 = c1t + off2p;

            #pragma unroll 4
            for (int t = 0; t < 128; ++t) {
                int m = s_meta[t];
                int i1 = m & 63;
                int i2 = (m >> 6) & 63;
                int keep = (m >> 12) & 1;
                if (i1 == e) { sp1[t] = (c1 < CAP_) ? c1 : -1; ++c1; }
                if (i2 == e) {
                    if (keep) { sp2[t] = (c2 < CAP_) ? c2 : -1; ++c2; }
                    else        sp2[t] = -1;
                }
            }
        }
        __syncthreads();

        if (tid < 128) {
            const int t = tid;
            const int gt = chunk * 128 + t;
            int m = s_meta[t];
            int p1 = sp1[t], p2 = sp2[t];
            float* db = out + (size_t)gt * (E_ * CAP_);
            float* cb = out + OUTSZ_ + (size_t)gt * (E_ * CAP_);
            if (p1 >= 0) {
                int o = (m & 63) * CAP_ + p1;
                float v = s_g1[t];
                cb[o] = v;
                db[o] = (v > 0.f) ? 1.f : 0.f;
            }
            if (p2 >= 0) {
                int o = ((m >> 6) & 63) * CAP_ + p2;
                float v = s_g2[t];
                cb[o] = v;
                db[o] = (v > 0.f) ? 1.f : 0.f;
            }
        }
    } else if (blockIdx.x == NCHUNK_) {
        __shared__ float red[64];
        if (tid < 64) {
            const int e = tid;
            float a = 0.0f;
            #pragma unroll
            for (int b = 0; b < B_; ++b) {
                float px = 0.0f; int t1 = 0;
                #pragma unroll
                for (int c = 0; c < 16; ++c) {
                    int o = (b * 16 + c) * E_ + e;
                    px += g_proxyp[o];
                    t1 += g_hist1[o];
                }
                a += px * (float)t1;
            }
            red[e] = a;
        }
        __syncthreads();
        if (tid == 0) {
            float s = 0.0f;
            #pragma unroll
            for (int i = 0; i < 64; ++i) s += red[i];
            out[2 * OUTSZ_] = s * ((float)E_ / ((float)B_ * (float)N_ * (float)N_));
        }
    }
}

extern "C" void kernel_launch(void* const* d_in, const int* in_sizes, int n_in,
                              void* d_out, int out_size) {
    const float* x     = (const float*)d_in[0];
    const float* w     = (const float*)d_in[1];
    const float* noise = (const float*)d_in[2];
    float* out = (float*)d_out;

    const int dyn = (128 * S_AS + 64 * 64) * sizeof(float);   // 49,664 B
    cudaFuncSetAttribute(k_fused, cudaFuncAttributeMaxDynamicSharedMemorySize, dyn);

    k_fused<<<GRID_TOTAL, TPB_, dyn>>>(x, w, noise, out);
}

// round 11
// speedup vs baseline: 1.0839x; 1.0839x over previous
#include <cuda_runtime.h>
#include <cstdint>

#define B_    8
#define N_    2048
#define D_    1024
#define E_    64
#define CAP_  80
#define TOK_  (B_ * N_)                 // 16384
#define TPB_  256
#define NCHUNK_ 128                     // gate chunks (128 tokens each) == grid
#define OUTSZ_ 83886080ULL              // B*N*E*CAP
#define S_AS  65

#define ROW4_    1280L                  // float4 per token row (5120 floats)
#define BLK4_    163840L                // float4 per block per half (128 rows)
#define COMB4_   20971520L              // OUTSZ_/4
#define VTOT_    327680L                // 2*BLK4_ virtual float4 per block
#define CW_      33792L                 // compute-warp fill share
#define FW_      48128L                 // fill-warp fill share  (4*CW_+4*FW_=VTOT_)

// ---------------- scratch ----------------
__device__ int   g_hist1[NCHUNK_ * E_];
__device__ int   g_hist2[NCHUNK_ * E_];
__device__ float g_proxyp[NCHUNK_ * E_];
__device__ unsigned int g_done;         // monotonic publish counter (replay-safe)

extern __shared__ float dynsh[];

__device__ __forceinline__ void bar128() {
    asm volatile("bar.sync 1, 128;" ::: "memory");
}

// fill virtual range [lo,hi) of this block's region: v<BLK4_ -> dispatch half, else combine half
__device__ __forceinline__ void fill_virt(float4* __restrict__ o4, long dbase, long cbase,
                                          long lo, long hi, int lane) {
    const float4 z = make_float4(0.f, 0.f, 0.f, 0.f);
    #pragma unroll 4
    for (long v = lo + lane; v < hi; v += 32) {
        long idx = (v < BLK4_) ? (dbase + v) : (cbase + v);
        o4[idx] = z;
    }
}

__global__ __launch_bounds__(TPB_) void k_fused(
    const float* __restrict__ x,
    const float* __restrict__ w,
    const float* __restrict__ noise,
    float* __restrict__ out)
{
    const int tid  = threadIdx.x;
    const int wid  = tid >> 5;
    const int lane = tid & 31;
    const int chunk = blockIdx.x;
    float4* __restrict__ o4 = (float4*)out;

    const long dbase = (long)chunk * BLK4_;
    const long cbase = COMB4_ + (long)chunk * BLK4_ - BLK4_;   // pre-shifted for v>=BLK4_

    __shared__ int   s_meta[128];
    __shared__ float s_g1[128];
    __shared__ float s_g2[128];
    __shared__ float s_inv[128];
    __shared__ int   s_i1[128];
    __shared__ int   s_i2[128];
    __shared__ int   sp1[128];
    __shared__ int   sp2[128];
    __shared__ unsigned int s_target;
    __shared__ float red[64];

    if (wid >= 4) {
        // ---------- fill warps: start storing at cycle 0 ----------
        long lo = 4 * CW_ + (long)(wid - 4) * FW_;
        fill_virt(o4, dbase, cbase, lo, lo + FW_, lane);
    } else {
        // ---------- compute warps: GEMM + softmax + top2 ----------
        float* As = dynsh;                       // [128][S_AS]
        float* Ws = dynsh + 128 * S_AS;          // [64][64]

        const int ty  = tid >> 3;
        const int tx  = tid & 7;
        const int t0  = ty * 8;
        const int gt0 = chunk * 128;
        const float* xblk = x + (size_t)gt0 * D_;

        unsigned long long acc[8][4];
        #pragma unroll
        for (int i = 0; i < 8; ++i)
            #pragma unroll
            for (int j = 0; j < 4; ++j) acc[i][j] = 0ULL;

        for (int kc = 0; kc < 16; ++kc) {
            #pragma unroll
            for (int i = 0; i < 16; ++i) {
                int idx = tid + i * 128;
                int r = idx >> 4, c4 = idx & 15;
                float4 v = *(const float4*)(xblk + (size_t)r * D_ + kc * 64 + c4 * 4);
                float* p = &As[r * S_AS + c4 * 4];
                p[0] = v.x; p[1] = v.y; p[2] = v.z; p[3] = v.w;
            }
            #pragma unroll
            for (int i = 0; i < 8; ++i) {
                int idx = tid + i * 128;
                int kr = idx >> 4, c4 = idx & 15;
                float4 v = *(const float4*)(w + (size_t)(kc * 64 + kr) * E_ + c4 * 4);
                *(float4*)&Ws[kr * 64 + c4 * 4] = v;
            }
            bar128();

            #pragma unroll 8
            for (int k = 0; k < 64; ++k) {
                unsigned long long a2[8], w2[4];
                #pragma unroll
                for (int i = 0; i < 8; ++i) {
                    float a = As[(t0 + i) * S_AS + k];
                    asm("mov.b64 %0, {%1, %1};" : "=l"(a2[i]) : "f"(a));
                }
                #pragma unroll
                for (int j = 0; j < 4; ++j)
                    w2[j] = *(const unsigned long long*)&Ws[k * 64 + 2 * tx + 16 * j];
                #pragma unroll
                for (int i = 0; i < 8; ++i)
                    #pragma unroll
                    for (int j = 0; j < 4; ++j)
                        asm("fma.rn.f32x2 %0, %1, %2, %0;" : "+l"(acc[i][j]) : "l"(a2[i]), "l"(w2[j]));
            }
            bar128();
        }

        // logits -> As[t][e]
        #pragma unroll
        for (int i = 0; i < 8; ++i)
            #pragma unroll
            for (int j = 0; j < 4; ++j) {
                float lo, hi;
                asm("mov.b64 {%0, %1}, %2;" : "=f"(lo), "=f"(hi) : "l"(acc[i][j]));
                As[(t0 + i) * S_AS + 2 * tx + 16 * j]     = lo;
                As[(t0 + i) * S_AS + 2 * tx + 16 * j + 1] = hi;
            }
        bar128();

        // per-token: softmax + top2 + gates
        {
            const int t = tid;
            float m1 = -1e30f, m2 = -1e30f;
            int i1 = 0, i2 = 0;
            #pragma unroll 8
            for (int e = 0; e < E_; ++e) {
                float l = As[t * S_AS + e];
                if (l > m1) { m2 = m1; i2 = i1; m1 = l; i1 = e; }
                else if (l > m2) { m2 = l; i2 = e; }
            }
            float s = 0.0f;
            #pragma unroll 8
            for (int e = 0; e < E_; ++e) {
                float p = expf(As[t * S_AS + e] - m1);
                As[t * S_AS + e] = p;
                s += p;
            }
            float inv = 1.0f / s;
            float g1 = inv;
            float g2 = expf(m2 - m1) * inv;
            float den = g1 + g2 + 1e-9f;
            g1 /= den; g2 /= den;

            int keep = (noise[chunk * 128 + t] < (g2 / 0.2f)) ? 1 : 0;
            s_meta[t] = i1 | (i2 << 6) | (keep << 12);
            s_g1[t] = g1; s_g2[t] = g2;
            s_i1[t] = i1;
            s_i2[t] = keep ? i2 : -1;
            s_inv[t] = inv;
        }
        bar128();

        // per-expert partials -> global
        if (tid < E_) {
            const int e = tid;
            float ps = 0.0f; int c1 = 0, c2 = 0;
            #pragma unroll 4
            for (int t = 0; t < 128; ++t) {
                ps += As[t * S_AS + e] * s_inv[t];
                c1 += (s_i1[t] == e);
                c2 += (s_i2[t] == e);
            }
            int o = chunk * E_ + e;
            g_proxyp[o] = ps;
            g_hist1[o] = c1;
            g_hist2[o] = c2;
        }
        bar128();                                  // hists visible to tid0 (cta scope)

        // publish: fence + monotonic counter
        if (tid == 0) {
            asm volatile("membar.gl;" ::: "memory");
            unsigned int old = atomicAdd(&g_done, 1u);
            s_target = old - (old % (unsigned)NCHUNK_) + (unsigned)NCHUNK_;
        }

        // compute warps' fill share (counter fills in the background)
        {
            long lo = (long)wid * CW_;
            fill_virt(o4, dbase, cbase, lo, lo + CW_, lane);
        }

        // wait for all chunks' hists (published ~long ago) and build offsets + scan
        if (tid == 0) {
            unsigned int v;
            do {
                asm volatile("ld.acquire.gpu.u32 %0, [%1];" : "=r"(v) : "l"(&g_done));
            } while (v < s_target);
        }
        bar128();

        if (tid < E_) {
            const int e = tid;
            const int b = chunk >> 4;
            const int myc = chunk & 15;
            const int cg0 = b * 16;
            int off1 = 0, tot1 = 0, off2p = 0;
            #pragma unroll
            for (int c = 0; c < 16; ++c) {
                int h1 = g_hist1[(cg0 + c) * E_ + e];
                int h2 = g_hist2[(cg0 + c) * E_ + e];
                if (c < myc) { off1 += h1; off2p += h2; }
                tot1 += h1;
            }
            int c1t = tot1 < CAP_ ? tot1 : CAP_;
            int c1 = off1;
            int c2 = c1t + off2p;

            #pragma unroll 4
            for (int t = 0; t < 128; ++t) {
                int m = s_meta[t];
                int i1 = m & 63;
                int i2 = (m >> 6) & 63;
                int keep = (m >> 12) & 1;
                if (i1 == e) { sp1[t] = (c1 < CAP_) ? c1 : -1; ++c1; }
                if (i2 == e) {
                    if (keep) { sp2[t] = (c2 < CAP_) ? c2 : -1; ++c2; }
                    else        sp2[t] = -1;
                }
            }
        }
    }

    // join: own-region fill complete + scan results ready
    __syncthreads();

    // scatter into own (just-filled, same-CTA-ordered) rows
    if (tid < 128) {
        const int t = tid;
        const int gt = chunk * 128 + t;
        int m = s_meta[t];
        int p1 = sp1[t], p2 = sp2[t];
        float* db = out + (size_t)gt * (E_ * CAP_);
        float* cb = out + OUTSZ_ + (size_t)gt * (E_ * CAP_);
        if (p1 >= 0) {
            int o = (m & 63) * CAP_ + p1;
            float v = s_g1[t];
            cb[o] = v;
            db[o] = (v > 0.f) ? 1.f : 0.f;
        }
        if (p2 >= 0) {
            int o = ((m >> 6) & 63) * CAP_ + p2;
            float v = s_g2[t];
            cb[o] = v;
            db[o] = (v > 0.f) ? 1.f : 0.f;
        }
    }

    // loss: block 0 (all hists/proxies long visible via its acquire)
    if (blockIdx.x == 0) {
        if (tid < 64) {
            const int e = tid;
            float a = 0.0f;
            #pragma unroll
            for (int b = 0; b < B_; ++b) {
                float px = 0.0f; int t1 = 0;
                #pragma unroll
                for (int c = 0; c < 16; ++c) {
                    int o = (b * 16 + c) * E_ + e;
                    px += g_proxyp[o];
                    t1 += g_hist1[o];
                }
                a += px * (float)t1;
            }
            red[e] = a;
        }
        __syncthreads();
        if (tid == 0) {
            float s = 0.0f;
            #pragma unroll
            for (int i = 0; i < 64; ++i) s += red[i];
            out[2 * OUTSZ_] = s * ((float)E_ / ((float)B_ * (float)N_ * (float)N_));
        }
    }
}

extern "C" void kernel_launch(void* const* d_in, const int* in_sizes, int n_in,
                              void* d_out, int out_size) {
    const float* x     = (const float*)d_in[0];
    const float* w     = (const float*)d_in[1];
    const float* noise = (const float*)d_in[2];
    float* out = (float*)d_out;

    const int dyn = (128 * S_AS + 64 * 64) * sizeof(float);   // 49,664 B
    cudaFuncSetAttribute(k_fused, cudaFuncAttributeMaxDynamicSharedMemorySize, dyn);

    k_fused<<<NCHUNK_, TPB_, dyn>>>(x, w, noise, out);
}

// round 13
// speedup vs baseline: 1.2213x; 1.1268x over previous
#include <cuda_runtime.h>
#include <cstdint>

#define B_    8
#define N_    2048
#define D_    1024
#define E_    64
#define CAP_  80
#define TOK_  (B_ * N_)                 // 16384
#define TPB_  256
#define NCHUNK_ 128                     // gate chunks (128 tokens each) == grid
#define OUTSZ_ 83886080ULL              // B*N*E*CAP
#define S_AS  65

#define BLK4_    163840L                // float4 per block per half (128 rows * 1280)
#define COMB4_   20971520L              // OUTSZ_/4
#define HALF_BYTES_ 2621440L            // BLK4_*16 per half per block
#define CHUNK_BYTES_ 16384
#define NCHUNKS_HALF_ 160               // HALF_BYTES_/CHUNK_BYTES_

// ---------------- scratch ----------------
__device__ int   g_hist1[NCHUNK_ * E_];
__device__ int   g_hist2[NCHUNK_ * E_];
__device__ float g_proxyp[NCHUNK_ * E_];
__device__ unsigned int g_done;         // monotonic publish counter (replay-safe)

extern __shared__ float dynsh[];

__device__ __forceinline__ void bar128() {
    asm volatile("bar.sync 1, 128;" ::: "memory");
}
__device__ __forceinline__ void barfill() {
    asm volatile("bar.sync 2, 128;" ::: "memory");      // fill warps (wid 4..7)
}

__device__ __forceinline__ uint32_t smem_u32(const void* p) {
    uint32_t a;
    asm("{ .reg .u64 t; cvta.to.shared.u64 t, %1; cvt.u32.u64 %0, t; }" : "=r"(a) : "l"(p));
    return a;
}

__device__ __forceinline__ void bulk_s2g(const char* g, uint32_t s, int bytes) {
    asm volatile("cp.async.bulk.global.shared::cta.bulk_group [%0], [%1], %2;"
                 :: "l"(g), "r"(s), "r"(bytes) : "memory");
}

__global__ __launch_bounds__(TPB_) void k_fused(
    const float* __restrict__ x,
    const float* __restrict__ w,
    const float* __restrict__ noise,
    float* __restrict__ out)
{
    const int tid  = threadIdx.x;
    const int wid  = tid >> 5;
    const int lane = tid & 31;
    const int chunk = blockIdx.x;

    __shared__ __align__(128) float4 s_zero[CHUNK_BYTES_ / 16];   // 16 KB staging
    __shared__ int   s_meta[128];
    __shared__ float s_g1[128];
    __shared__ float s_g2[128];
    __shared__ float s_inv[128];
    __shared__ int   s_i1[128];
    __shared__ int   s_i2[128];
    __shared__ int   sp1[128];
    __shared__ int   sp2[128];
    __shared__ unsigned int s_target;
    __shared__ float red[64];

    if (wid >= 4) {
        // ---------- fill warps: zero staging, then TMA bulk-store the block's region ----------
        const int ft = tid - 128;                     // 0..127
        const float4 z = make_float4(0.f, 0.f, 0.f, 0.f);
        #pragma unroll
        for (int i = 0; i < (CHUNK_BYTES_ / 16) / 128; ++i)
            s_zero[ft + i * 128] = z;
        asm volatile("fence.proxy.async;" ::: "memory");
        barfill();

        if ((wid == 4 || wid == 5) && lane == 0) {
            const uint32_t saddr = smem_u32(s_zero);
            const char* gbase = (const char*)out +
                ((wid == 4) ? ((long)chunk * BLK4_ * 16)
                            : ((COMB4_ + (long)chunk * BLK4_) * 16));
            for (int c = 0; c < NCHUNKS_HALF_; ++c)
                bulk_s2g(gbase + (long)c * CHUNK_BYTES_, saddr, CHUNK_BYTES_);
            asm volatile("cp.async.bulk.commit_group;" ::: "memory");
            asm volatile("cp.async.bulk.wait_group 0;" ::: "memory");
        }
    } else {
        // ---------- compute warps: GEMM + softmax + top2 ----------
        float* As = dynsh;                       // [128][S_AS]
        float* Ws = dynsh + 128 * S_AS;          // [64][64]

        const int ty  = tid >> 3;
        const int tx  = tid & 7;
        const int t0  = ty * 8;
        const int gt0 = chunk * 128;
        const float* xblk = x + (size_t)gt0 * D_;

        unsigned long long acc[8][4];
        #pragma unroll
        for (int i = 0; i < 8; ++i)
            #pragma unroll
            for (int j = 0; j < 4; ++j) acc[i][j] = 0ULL;

        for (int kc = 0; kc < 16; ++kc) {
            #pragma unroll
            for (int i = 0; i < 16; ++i) {
                int idx = tid + i * 128;
                int r = idx >> 4, c4 = idx & 15;
                float4 v = *(const float4*)(xblk + (size_t)r * D_ + kc * 64 + c4 * 4);
                float* p = &As[r * S_AS + c4 * 4];
                p[0] = v.x; p[1] = v.y; p[2] = v.z; p[3] = v.w;
            }
            #pragma unroll
            for (int i = 0; i < 8; ++i) {
                int idx = tid + i * 128;
                int kr = idx >> 4, c4 = idx & 15;
                float4 v = *(const float4*)(w + (size_t)(kc * 64 + kr) * E_ + c4 * 4);
                *(float4*)&Ws[kr * 64 + c4 * 4] = v;
            }
            bar128();

            #pragma unroll 8
            for (int k = 0; k < 64; ++k) {
                unsigned long long a2[8], w2[4];
                #pragma unroll
                for (int i = 0; i < 8; ++i) {
                    float a = As[(t0 + i) * S_AS + k];
                    asm("mov.b64 %0, {%1, %1};" : "=l"(a2[i]) : "f"(a));
                }
                #pragma unroll
                for (int j = 0; j < 4; ++j)
                    w2[j] = *(const unsigned long long*)&Ws[k * 64 + 2 * tx + 16 * j];
                #pragma unroll
                for (int i = 0; i < 8; ++i)
                    #pragma unroll
                    for (int j = 0; j < 4; ++j)
                        asm("fma.rn.f32x2 %0, %1, %2, %0;" : "+l"(acc[i][j]) : "l"(a2[i]), "l"(w2[j]));
            }
            bar128();
        }

        // logits -> As[t][e]
        #pragma unroll
        for (int i = 0; i < 8; ++i)
            #pragma unroll
            for (int j = 0; j < 4; ++j) {
                float lo, hi;
                asm("mov.b64 {%0, %1}, %2;" : "=f"(lo), "=f"(hi) : "l"(acc[i][j]));
                As[(t0 + i) * S_AS + 2 * tx + 16 * j]     = lo;
                As[(t0 + i) * S_AS + 2 * tx + 16 * j + 1] = hi;
            }
        bar128();

        // per-token: softmax + top2 + gates
        {
            const int t = tid;
            float m1 = -1e30f, m2 = -1e30f;
            int i1 = 0, i2 = 0;
            #pragma unroll 8
            for (int e = 0; e < E_; ++e) {
                float l = As[t * S_AS + e];
                if (l > m1) { m2 = m1; i2 = i1; m1 = l; i1 = e; }
                else if (l > m2) { m2 = l; i2 = e; }
            }
            float s = 0.0f;
            #pragma unroll 8
            for (int e = 0; e < E_; ++e) {
                float p = expf(As[t * S_AS + e] - m1);
                As[t * S_AS + e] = p;
                s += p;
            }
            float inv = 1.0f / s;
            float g1 = inv;
            float g2 = expf(m2 - m1) * inv;
            float den = g1 + g2 + 1e-9f;
            g1 /= den; g2 /= den;

            int keep = (noise[chunk * 128 + t] < (g2 / 0.2f)) ? 1 : 0;
            s_meta[t] = i1 | (i2 << 6) | (keep << 12);
            s_g1[t] = g1; s_g2[t] = g2;
            s_i1[t] = i1;
            s_i2[t] = keep ? i2 : -1;
            s_inv[t] = inv;
        }
        bar128();

        // per-expert partials -> global
        if (tid < E_) {
            const int e = tid;
            float ps = 0.0f; int c1 = 0, c2 = 0;
            #pragma unroll 4
            for (int t = 0; t < 128; ++t) {
                ps += As[t * S_AS + e] * s_inv[t];
                c1 += (s_i1[t] == e);
                c2 += (s_i2[t] == e);
            }
            int o = chunk * E_ + e;
            g_proxyp[o] = ps;
            g_hist1[o] = c1;
            g_hist2[o] = c2;
        }
        bar128();

        // publish: fence + monotonic counter
        if (tid == 0) {
            asm volatile("membar.gl;" ::: "memory");
            unsigned int old = atomicAdd(&g_done, 1u);
            s_target = old - (old % (unsigned)NCHUNK_) + (unsigned)NCHUNK_;
        }
        bar128();

        // wait for all chunks' hists, then offsets + local scan
        if (tid == 0) {
            unsigned int v;
            do {
                asm volatile("ld.acquire.gpu.u32 %0, [%1];" : "=r"(v) : "l"(&g_done));
            } while (v < s_target);
        }
        bar128();

        if (tid < E_) {
            const int e = tid;
            const int b = chunk >> 4;
            const int myc = chunk & 15;
            const int cg0 = b * 16;
            int off1 = 0, tot1 = 0, off2p = 0;
            #pragma unroll
            for (int c = 0; c < 16; ++c) {
                int h1 = g_hist1[(cg0 + c) * E_ + e];
                int h2 = g_hist2[(cg0 + c) * E_ + e];
                if (c < myc) { off1 += h1; off2p += h2; }
                tot1 += h1;
            }
            int c1t = tot1 < CAP_ ? tot1 : CAP_;
            int c1 = off1;
            int c2 = c1t + off2p;

            #pragma unroll 4
            for (int t = 0; t < 128; ++t) {
                int m = s_meta[t];
                int i1 = m & 63;
                int i2 = (m >> 6) & 63;
                int keep = (m >> 12) & 1;
                if (i1 == e) { sp1[t] = (c1 < CAP_) ? c1 : -1; ++c1; }
                if (i2 == e) {
                    if (keep) { sp2[t] = (c2 < CAP_) ? c2 : -1; ++c2; }
                    else        sp2[t] = -1;
                }
            }
        }
    }

    // join: TMA fill complete (wait_group 0) + scan ready
    __syncthreads();

    // scatter into own just-filled rows
    if (tid < 128) {
        const int t = tid;
        const int gt = chunk * 128 + t;
        int m = s_meta[t];
        int p1 = sp1[t], p2 = sp2[t];
        float* db = out + (size_t)gt * (E_ * CAP_);
        float* cb = out + OUTSZ_ + (size_t)gt * (E_ * CAP_);
        if (p1 >= 0) {
            int o = (m & 63) * CAP_ + p1;
            float v = s_g1[t];
            cb[o] = v;
            db[o] = (v > 0.f) ? 1.f : 0.f;
        }
        if (p2 >= 0) {
            int o = ((m >> 6) & 63) * CAP_ + p2;
            float v = s_g2[t];
            cb[o] = v;
            db[o] = (v > 0.f) ? 1.f : 0.f;
        }
    }

    // loss: block 0
    if (blockIdx.x == 0) {
        if (tid < 64) {
            const int e = tid;
            float a = 0.0f;
            #pragma unroll
            for (int b = 0; b < B_; ++b) {
                float px = 0.0f; int t1 = 0;
                #pragma unroll
                for (int c = 0; c < 16; ++c) {
                    int o = (b * 16 + c) * E_ + e;
                    px += g_proxyp[o];
                    t1 += g_hist1[o];
                }
                a += px * (float)t1;
            }
            red[e] = a;
        }
        __syncthreads();
        if (tid == 0) {
            float s = 0.0f;
            #pragma unroll
            for (int i = 0; i < 64; ++i) s += red[i];
            out[2 * OUTSZ_] = s * ((float)E_ / ((float)B_ * (float)N_ * (float)N_));
        }
    }
}

extern "C" void kernel_launch(void* const* d_in, const int* in_sizes, int n_in,
                              void* d_out, int out_size) {
    const float* x     = (const float*)d_in[0];
    const float* w     = (const float*)d_in[1];
    const float* noise = (const float*)d_in[2];
    float* out = (float*)d_out;

    const int dyn = (128 * S_AS + 64 * 64) * sizeof(float);   // 49,664 B
    cudaFuncSetAttribute(k_fused, cudaFuncAttributeMaxDynamicSharedMemorySize, dyn);

    k_fused<<<NCHUNK_, TPB_, dyn>>>(x, w, noise, out);
}

// round 14
// speedup vs baseline: 1.2681x; 1.0383x over previous
#include <cuda_runtime.h>
#include <cstdint>

#define B_    8
#define N_    2048
#define D_    1024
#define E_    64
#define CAP_  80
#define TOK_  (B_ * N_)                 // 16384
#define TPB_  256
#define NCHUNK_ 128                     // gate chunks (128 tokens each) == grid
#define OUTSZ_ 83886080ULL              // B*N*E*CAP
#define S_AS  65

#define BLK4_    163840L                // float4 per block per half (128 rows * 1280)
#define COMB4_   20971520L              // OUTSZ_/4
#define HALF_BYTES_ 2621440L            // per half per block
#define CHUNK_BYTES_ 32768              // 32 KB staging / bulk chunk
#define NCHUNKS_HALF_ 80                // HALF_BYTES_/CHUNK_BYTES_
#define CHUNKS_PER_WARP_ 40             // 2 warps per half

// ---------------- scratch ----------------
__device__ int   g_hist1[NCHUNK_ * E_];
__device__ int   g_hist2[NCHUNK_ * E_];
__device__ float g_proxyp[NCHUNK_ * E_];
__device__ unsigned int g_done;         // monotonic publish counter (replay-safe)

extern __shared__ float dynsh[];

__device__ __forceinline__ void bar128() {
    asm volatile("bar.sync 1, 128;" ::: "memory");
}
__device__ __forceinline__ void barfill() {
    asm volatile("bar.sync 2, 128;" ::: "memory");      // fill warps (wid 4..7)
}

__device__ __forceinline__ uint32_t smem_u32(const void* p) {
    uint32_t a;
    asm("{ .reg .u64 t; cvta.to.shared.u64 t, %1; cvt.u32.u64 %0, t; }" : "=r"(a) : "l"(p));
    return a;
}

__device__ __forceinline__ void bulk_s2g(const char* g, uint32_t s, int bytes) {
    asm volatile("cp.async.bulk.global.shared::cta.bulk_group [%0], [%1], %2;"
                 :: "l"(g), "r"(s), "r"(bytes) : "memory");
}

__global__ __launch_bounds__(TPB_) void k_fused(
    const float* __restrict__ x,
    const float* __restrict__ w,
    const float* __restrict__ noise,
    float* __restrict__ out)
{
    const int tid  = threadIdx.x;
    const int wid  = tid >> 5;
    const int lane = tid & 31;
    const int chunk = blockIdx.x;

    __shared__ __align__(128) float4 s_zero[CHUNK_BYTES_ / 16];   // 32 KB staging
    __shared__ int   s_meta[128];
    __shared__ float s_g1[128];
    __shared__ float s_g2[128];
    __shared__ float s_inv[128];
    __shared__ int   s_i1[128];
    __shared__ int   s_i2[128];
    __shared__ int   sp1[128];
    __shared__ int   sp2[128];
    __shared__ unsigned int s_target;
    __shared__ float red[64];

    if (wid >= 4) {
        // ---------- fill warps: zero staging, then 4 parallel TMA bulk chains ----------
        const int ft = tid - 128;                     // 0..127
        const float4 z = make_float4(0.f, 0.f, 0.f, 0.f);
        #pragma unroll
        for (int i = 0; i < (CHUNK_BYTES_ / 16) / 128; ++i)
            s_zero[ft + i * 128] = z;
        asm volatile("fence.proxy.async;" ::: "memory");
        barfill();

        if (lane == 0) {
            const uint32_t saddr = smem_u32(s_zero);
            // wid 4,5 -> dispatch half; wid 6,7 -> combine half; each covers 40 chunks
            const int half = (wid - 4) >> 1;          // 0 or 1
            const int sub  = (wid - 4) & 1;           // 0 or 1
            const char* gbase = (const char*)out +
                (half == 0 ? ((long)chunk * BLK4_ * 16)
                           : ((COMB4_ + (long)chunk * BLK4_) * 16))
                + (long)sub * CHUNKS_PER_WARP_ * CHUNK_BYTES_;
            #pragma unroll 4
            for (int c = 0; c < CHUNKS_PER_WARP_; ++c)
                bulk_s2g(gbase + (long)c * CHUNK_BYTES_, saddr, CHUNK_BYTES_);
            asm volatile("cp.async.bulk.commit_group;" ::: "memory");
            asm volatile("cp.async.bulk.wait_group 0;" ::: "memory");
        }
    } else {
        // ---------- compute warps: GEMM + softmax + top2 ----------
        float* As = dynsh;                       // [128][S_AS]
        float* Ws = dynsh + 128 * S_AS;          // [64][64]

        const int ty  = tid >> 3;
        const int tx  = tid & 7;
        const int t0  = ty * 8;
        const int gt0 = chunk * 128;
        const float* xblk = x + (size_t)gt0 * D_;

        unsigned long long acc[8][4];
        #pragma unroll
        for (int i = 0; i < 8; ++i)
            #pragma unroll
            for (int j = 0; j < 4; ++j) acc[i][j] = 0ULL;

        for (int kc = 0; kc < 16; ++kc) {
            #pragma unroll
            for (int i = 0; i < 16; ++i) {
                int idx = tid + i * 128;
                int r = idx >> 4, c4 = idx & 15;
                float4 v = *(const float4*)(xblk + (size_t)r * D_ + kc * 64 + c4 * 4);
                float* p = &As[r * S_AS + c4 * 4];
                p[0] = v.x; p[1] = v.y; p[2] = v.z; p[3] = v.w;
            }
            #pragma unroll
            for (int i = 0; i < 8; ++i) {
                int idx = tid + i * 128;
                int kr = idx >> 4, c4 = idx & 15;
                float4 v = *(const float4*)(w + (size_t)(kc * 64 + kr) * E_ + c4 * 4);
                *(float4*)&Ws[kr * 64 + c4 * 4] = v;
            }
            bar128();

            #pragma unroll 8
            for (int k = 0; k < 64; ++k) {
                unsigned long long a2[8], w2[4];
                #pragma unroll
                for (int i = 0; i < 8; ++i) {
                    float a = As[(t0 + i) * S_AS + k];
                    asm("mov.b64 %0, {%1, %1};" : "=l"(a2[i]) : "f"(a));
                }
                #pragma unroll
                for (int j = 0; j < 4; ++j)
                    w2[j] = *(const unsigned long long*)&Ws[k * 64 + 2 * tx + 16 * j];
                #pragma unroll
                for (int i = 0; i < 8; ++i)
                    #pragma unroll
                    for (int j = 0; j < 4; ++j)
                        asm("fma.rn.f32x2 %0, %1, %2, %0;" : "+l"(acc[i][j]) : "l"(a2[i]), "l"(w2[j]));
            }
            bar128();
        }

        // logits -> As[t][e]
        #pragma unroll
        for (int i = 0; i < 8; ++i)
            #pragma unroll
            for (int j = 0; j < 4; ++j) {
                float lo, hi;
                asm("mov.b64 {%0, %1}, %2;" : "=f"(lo), "=f"(hi) : "l"(acc[i][j]));
                As[(t0 + i) * S_AS + 2 * tx + 16 * j]     = lo;
                As[(t0 + i) * S_AS + 2 * tx + 16 * j + 1] = hi;
            }
        bar128();

        // per-token: softmax + top2 + gates
        {
            const int t = tid;
            float m1 = -1e30f, m2 = -1e30f;
            int i1 = 0, i2 = 0;
            #pragma unroll 8
            for (int e = 0; e < E_; ++e) {
                float l = As[t * S_AS + e];
                if (l > m1) { m2 = m1; i2 = i1; m1 = l; i1 = e; }
                else if (l > m2) { m2 = l; i2 = e; }
            }
            float s = 0.0f;
            #pragma unroll 8
            for (int e = 0; e < E_; ++e) {
                float p = expf(As[t * S_AS + e] - m1);
                As[t * S_AS + e] = p;
                s += p;
            }
            float inv = 1.0f / s;
            float g1 = inv;
            float g2 = expf(m2 - m1) * inv;
            float den = g1 + g2 + 1e-9f;
            g1 /= den; g2 /= den;

            int keep = (noise[chunk * 128 + t] < (g2 / 0.2f)) ? 1 : 0;
            s_meta[t] = i1 | (i2 << 6) | (keep << 12);
            s_g1[t] = g1; s_g2[t] = g2;
            s_i1[t] = i1;
            s_i2[t] = keep ? i2 : -1;
            s_inv[t] = inv;
        }
        bar128();

        // per-expert partials -> global
        if (tid < E_) {
            const int e = tid;
            float ps = 0.0f; int c1 = 0, c2 = 0;
            #pragma unroll 4
            for (int t = 0; t < 128; ++t) {
                ps += As[t * S_AS + e] * s_inv[t];
                c1 += (s_i1[t] == e);
                c2 += (s_i2[t] == e);
            }
            int o = chunk * E_ + e;
            g_proxyp[o] = ps;
            g_hist1[o] = c1;
            g_hist2[o] = c2;
        }
        bar128();

        // publish: fence + monotonic counter
        if (tid == 0) {
            asm volatile("membar.gl;" ::: "memory");
            unsigned int old = atomicAdd(&g_done, 1u);
            s_target = old - (old % (unsigned)NCHUNK_) + (unsigned)NCHUNK_;
        }
        bar128();

        // wait for all chunks' hists, then offsets + local scan
        if (tid == 0) {
            unsigned int v;
            do {
                asm volatile("ld.acquire.gpu.u32 %0, [%1];" : "=r"(v) : "l"(&g_done));
            } while (v < s_target);
        }
        bar128();

        if (tid < E_) {
            const int e = tid;
            const int b = chunk >> 4;
            const int myc = chunk & 15;
            const int cg0 = b * 16;
            int off1 = 0, tot1 = 0, off2p = 0;
            #pragma unroll
            for (int c = 0; c < 16; ++c) {
                int h1 = g_hist1[(cg0 + c) * E_ + e];
                int h2 = g_hist2[(cg0 + c) * E_ + e];
                if (c < myc) { off1 += h1; off2p += h2; }
                tot1 += h1;
            }
            int c1t = tot1 < CAP_ ? tot1 : CAP_;
            int c1 = off1;
            int c2 = c1t + off2p;

            #pragma unroll 4
            for (int t = 0; t < 128; ++t) {
                int m = s_meta[t];
                int i1 = m & 63;
                int i2 = (m >> 6) & 63;
                int keep = (m >> 12) & 1;
                if (i1 == e) { sp1[t] = (c1 < CAP_) ? c1 : -1; ++c1; }
                if (i2 == e) {
                    if (keep) { sp2[t] = (c2 < CAP_) ? c2 : -1; ++c2; }
                    else        sp2[t] = -1;
                }
            }
        }
    }

    // join: all 4 TMA chains complete (each warp's wait_group 0) + scan ready
    __syncthreads();

    // scatter into own just-filled rows
    if (tid < 128) {
        const int t = tid;
        const int gt = chunk * 128 + t;
        int m = s_meta[t];
        int p1 = sp1[t], p2 = sp2[t];
        float* db = out + (size_t)gt * (E_ * CAP_);
        float* cb = out + OUTSZ_ + (size_t)gt * (E_ * CAP_);
        if (p1 >= 0) {
            int o = (m & 63) * CAP_ + p1;
            float v = s_g1[t];
            cb[o] = v;
            db[o] = (v > 0.f) ? 1.f : 0.f;
        }
        if (p2 >= 0) {
            int o = ((m >> 6) & 63) * CAP_ + p2;
            float v = s_g2[t];
            cb[o] = v;
            db[o] = (v > 0.f) ? 1.f : 0.f;
        }
    }

    // loss: block 0
    if (blockIdx.x == 0) {
        if (tid < 64) {
            const int e = tid;
            float a = 0.0f;
            #pragma unroll
            for (int b = 0; b < B_; ++b) {
                float px = 0.0f; int t1 = 0;
                #pragma unroll
                for (int c = 0; c < 16; ++c) {
                    int o = (b * 16 + c) * E_ + e;
                    px += g_proxyp[o];
                    t1 += g_hist1[o];
                }
                a += px * (float)t1;
            }
            red[e] = a;
        }
        __syncthreads();
        if (tid == 0) {
            float s = 0.0f;
            #pragma unroll
            for (int i = 0; i < 64; ++i) s += red[i];
            out[2 * OUTSZ_] = s * ((float)E_ / ((float)B_ * (float)N_ * (float)N_));
        }
    }
}

extern "C" void kernel_launch(void* const* d_in, const int* in_sizes, int n_in,
                              void* d_out, int out_size) {
    const float* x     = (const float*)d_in[0];
    const float* w     = (const float*)d_in[1];
    const float* noise = (const float*)d_in[2];
    float* out = (float*)d_out;

    const int dyn = (128 * S_AS + 64 * 64) * sizeof(float);   // 49,664 B
    cudaFuncSetAttribute(k_fused, cudaFuncAttributeMaxDynamicSharedMemorySize, dyn);

    k_fused<<<NCHUNK_, TPB_, dyn>>>(x, w, noise, out);
}